// round 7
// baseline (speedup 1.0000x reference)
#include <cuda_runtime.h>

#define T_DIM  1024
#define F_DIM  500
#define B_DIM  64
#define O_DIM  10
#define BO     (B_DIM * O_DIM)     // 640
#define FSPLIT 10
#define FCH    (F_DIM / FSPLIT)    // 50
#define T4     (T_DIM / 4)         // 256
#define FPAD4  32                  // front pad (zeros) for segment warmup
#define BPAD4  8                   // back pad for prefetch overrun

// Scratch (static device globals, zero-initialized at module load; pads never written)
__device__ float  g_part[FSPLIT][BO][T_DIM];           // 26.2 MB, [z][bo][t]
__device__ float4 g_u4[(FPAD4 + T4 + BPAD4) * BO];     // tiled [t4][bo], ~3 MB

__device__ __forceinline__ float fast_sigmoid(float x) {
    float e, r;
    asm("ex2.approx.f32 %0, %1;" : "=f"(e) : "f"(x * -1.4426950408889634f));
    asm("rcp.approx.f32 %0, %1;" : "=f"(r) : "f"(1.0f + e));
    return r;
}

// ---------------------------------------------------------------------------
// Kernel 1: partial[z][b*10+o][t] = sum_{f in chunk z} W[o,f]*sigmoid(in[b,f,t])
// grid (4, 64, 10) = 2560 CTAs (~17/SM offered), 128 threads, 2 t/thread.
// Scalar FFMA (R2 formulation, lowest regs), 5-deep clamped prefetch (MLP=5).
// ---------------------------------------------------------------------------
__global__ __launch_bounds__(128) void k_proj(const float* __restrict__ in,
                                              const float* __restrict__ W) {
    __shared__ float Wt[FCH * 12];     // [f][o], stride 12 floats (16B-aligned rows)

    const int z  = blockIdx.z;
    const int fs = z * FCH;
    for (int i = threadIdx.x; i < FCH * O_DIM; i += 128) {
        int o = i / FCH;
        int j = i - o * FCH;
        Wt[j * 12 + o] = W[o * F_DIM + fs + j];
    }
    __syncthreads();

    const int b  = blockIdx.y;
    const int t0 = blockIdx.x * 256 + threadIdx.x * 2;

    const float2* p = (const float2*)(in + (size_t)b * (F_DIM * T_DIM)
                                         + (size_t)fs * T_DIM + t0);
    const int fstride = T_DIM / 2;

    float acc0[O_DIM], acc1[O_DIM];
#pragma unroll
    for (int o = 0; o < O_DIM; o++) { acc0[o] = 0.0f; acc1[o] = 0.0f; }

    // 5-deep prefetch queue (FCH = 50 = 10 groups of 5)
    float2 pf[5];
#pragma unroll
    for (int j = 0; j < 5; j++) pf[j] = p[(size_t)j * fstride];

#pragma unroll 1
    for (int fb = 0; fb < FCH; fb += 5) {
        float2 cur[5];
#pragma unroll
        for (int j = 0; j < 5; j++) cur[j] = pf[j];

        // front-batched next-group loads; clamp keeps addresses in-chunk (no OOB)
#pragma unroll
        for (int j = 0; j < 5; j++) {
            int fn = fb + 5 + j;
            fn = (fn < FCH) ? fn : (FCH - 1);
            pf[j] = p[(size_t)fn * fstride];
        }

#pragma unroll
        for (int j = 0; j < 5; j++) {
            float s0 = fast_sigmoid(cur[j].x);
            float s1 = fast_sigmoid(cur[j].y);
            const float* row = Wt + (fb + j) * 12;
            float4 wa = *(const float4*)(row);
            float4 wb = *(const float4*)(row + 4);
            float2 wc = *(const float2*)(row + 8);
            float wv[O_DIM];
            wv[0] = wa.x; wv[1] = wa.y; wv[2] = wa.z; wv[3] = wa.w;
            wv[4] = wb.x; wv[5] = wb.y; wv[6] = wb.z; wv[7] = wb.w;
            wv[8] = wc.x; wv[9] = wc.y;
#pragma unroll
            for (int o = 0; o < O_DIM; o++) {
                acc0[o] = fmaf(s0, wv[o], acc0[o]);
                acc1[o] = fmaf(s1, wv[o], acc1[o]);
            }
        }
    }

    float* base = &g_part[z][b * O_DIM][0] + t0;
#pragma unroll
    for (int o = 0; o < O_DIM; o++) {
        float2 v; v.x = acc0[o]; v.y = acc1[o];
        *(float2*)(base + (size_t)o * T_DIM) = v;
    }
}

// ---------------------------------------------------------------------------
// Kernel 2: merge 10 partials + transpose into tiled layout g_u4[t4][bo].
// grid (20 bo-tiles, 8 t-tiles), 128 threads. smem 32x133 (conflict-free).
// ---------------------------------------------------------------------------
__global__ __launch_bounds__(128) void k_merge() {
    __shared__ float sm[32][133];
    const int bo0 = blockIdx.x * 32;
    const int t0  = blockIdx.y * 128;

    for (int i = threadIdx.x; i < 32 * 128; i += 128) {
        int r = i >> 7;          // bo within tile
        int c = i & 127;         // t within tile
        const float* pp = &g_part[0][bo0 + r][t0 + c];
        float s = pp[0];
#pragma unroll
        for (int zz = 1; zz < FSPLIT; zz++) s += pp[(size_t)zz * BO * T_DIM];
        sm[r][c] = s;
    }
    __syncthreads();

    for (int i = threadIdx.x; i < 32 * 32; i += 128) {
        int t4l = i >> 5;        // t4 within tile
        int bl  = i & 31;        // bo within tile
        float4 v;
        v.x = sm[bl][t4l * 4 + 0];
        v.y = sm[bl][t4l * 4 + 1];
        v.z = sm[bl][t4l * 4 + 2];
        v.w = sm[bl][t4l * 4 + 3];
        g_u4[(size_t)(FPAD4 + t0 / 4 + t4l) * BO + bo0 + bl] = v;
    }
}

// ---------------------------------------------------------------------------
// Kernel 3: segment-parallel IIR+LIF. grid (20 bo-tiles, 8 segments) x 32 thr.
// 128-step warmup from zero state (residual ~ dm^128 ~ 1e-13, below fp32 ulp;
// exact after any spike reset), then 128 output steps. Seg 0 warms up on the
// zero front-pad with zero bias -> state stays exactly zero.
// ---------------------------------------------------------------------------
__global__ __launch_bounds__(32) void k_lif(const float* __restrict__ a1v,
                                            const float* __restrict__ a2v,
                                            const float* __restrict__ bias,
                                            float* __restrict__ out) {
    __shared__ float4 tile[32 * 33];   // [t4][chain], pad 33

    const int lane = threadIdx.x;
    const int bo0  = blockIdx.x * 32;
    const int bo   = bo0 + lane;
    const int seg  = blockIdx.y;

    const float A1 = a1v[0];
    const float A2 = a2v[0];
    const float dm = 0.5f * (A1 + sqrtf(fmaf(A1, A1, 4.0f * A2)));
    const float bb  = bias[bo % O_DIM];
    const float bwu = (seg == 0) ? 0.0f : bb;   // warmup bias (seg 0: stay at zero)

    const float4* pu = g_u4 + (size_t)FPAD4 * BO + bo;   // index by t4 (can go -32)
    const int w0 = seg * 32 - 32;                        // warmup start t4

    float4 q[8];
#pragma unroll
    for (int j = 0; j < 8; j++) q[j] = pu[(ptrdiff_t)(w0 + j) * BO];

    float y1 = 0.0f, y2 = 0.0f, v = 0.0f;
    bool sp = false;

    // ---- warmup: 32 t4 (128 steps), no stores ----
    for (int g = 0; g < 4; g++) {
#pragma unroll
        for (int j = 0; j < 8; j++) {
            float4 xq = q[j];
            q[j] = pu[(ptrdiff_t)(w0 + g * 8 + j + 8) * BO];
#pragma unroll
            for (int k = 0; k < 4; k++) {
                float x = (k == 0) ? xq.x : (k == 1) ? xq.y : (k == 2) ? xq.z : xq.w;
                float y = fmaf(A1, y1, fmaf(A2, y2, x));
                y2 = y1; y1 = y;
                float psc = y + bwu;
                float vns = fmaf(dm, v, psc);
                v  = sp ? psc : vns;
                sp = (v > 1.0f);
            }
        }
    }

    // ---- main: 32 t4 (128 steps), spikes -> smem tile ----
    const int m0 = seg * 32;
    for (int g = 0; g < 4; g++) {
#pragma unroll
        for (int j = 0; j < 8; j++) {
            float4 xq = q[j];
            q[j] = pu[(ptrdiff_t)(m0 + g * 8 + j + 8) * BO];   // back-pad covers tail
            float4 os;
#pragma unroll
            for (int k = 0; k < 4; k++) {
                float x = (k == 0) ? xq.x : (k == 1) ? xq.y : (k == 2) ? xq.z : xq.w;
                float y = fmaf(A1, y1, fmaf(A2, y2, x));
                y2 = y1; y1 = y;
                float psc = y + bb;
                float vns = fmaf(dm, v, psc);
                v  = sp ? psc : vns;
                sp = (v > 1.0f);
                float s = sp ? 1.0f : 0.0f;
                if      (k == 0) os.x = s;
                else if (k == 1) os.y = s;
                else if (k == 2) os.z = s;
                else             os.w = s;
            }
            tile[(g * 8 + j) * 33 + lane] = os;
        }
    }
    __syncwarp();
#pragma unroll 4
    for (int r = 0; r < 32; r++) {
        float4 w = tile[lane * 33 + r];
        *(float4*)(out + (size_t)(bo0 + r) * T_DIM + seg * 128 + lane * 4) = w;
    }
}

// ---------------------------------------------------------------------------
extern "C" void kernel_launch(void* const* d_in, const int* in_sizes, int n_in,
                              void* d_out, int out_size) {
    const float* in  = (const float*)d_in[0];   // [64, 500, 1024]
    const float* a1  = (const float*)d_in[1];   // [500]
    const float* a2  = (const float*)d_in[2];   // [500]
    const float* W   = (const float*)d_in[3];   // [10, 500]
    const float* bv  = (const float*)d_in[4];   // [10]
    float* out = (float*)d_out;                 // [64, 10, 1024]

    k_proj<<<dim3(T_DIM / 256, B_DIM, FSPLIT), 128>>>(in, W);
    k_merge<<<dim3(BO / 32, T_DIM / 128), 128>>>();
    k_lif<<<dim3(BO / 32, T_DIM / 128), 32>>>(a1, a2, bv, out);
}

// round 9
// speedup vs baseline: 1.1071x; 1.1071x over previous
#include <cuda_runtime.h>

#define T_DIM  1024
#define F_DIM  500
#define B_DIM  64
#define O_DIM  10
#define BO     (B_DIM * O_DIM)     // 640
#define FSPLIT 10
#define FCH    (F_DIM / FSPLIT)    // 50

// Scratch (static device global, zero-initialized at module load)
__device__ float g_part[FSPLIT][BO][T_DIM];   // 26.2 MB, [z][bo][t]

__device__ __forceinline__ float fast_sigmoid(float x) {
    float e, r;
    asm("ex2.approx.f32 %0, %1;" : "=f"(e) : "f"(x * -1.4426950408889634f));
    asm("rcp.approx.f32 %0, %1;" : "=f"(r) : "f"(1.0f + e));
    return r;
}

// ---------------------------------------------------------------------------
// Kernel 1 (unchanged, measured 39.9us in R7):
// partial[z][b*10+o][t] = sum_{f in chunk z} W[o,f]*sigmoid(in[b,f,t])
// grid (4, 64, 10) = 2560 CTAs, 128 threads, 2 t/thread, 5-deep prefetch.
// ---------------------------------------------------------------------------
__global__ __launch_bounds__(128) void k_proj(const float* __restrict__ in,
                                              const float* __restrict__ W) {
    __shared__ float Wt[FCH * 12];     // [f][o], stride 12 floats

    const int z  = blockIdx.z;
    const int fs = z * FCH;
    for (int i = threadIdx.x; i < FCH * O_DIM; i += 128) {
        int o = i / FCH;
        int j = i - o * FCH;
        Wt[j * 12 + o] = W[o * F_DIM + fs + j];
    }
    __syncthreads();

    const int b  = blockIdx.y;
    const int t0 = blockIdx.x * 256 + threadIdx.x * 2;

    const float2* p = (const float2*)(in + (size_t)b * (F_DIM * T_DIM)
                                         + (size_t)fs * T_DIM + t0);
    const int fstride = T_DIM / 2;

    float acc0[O_DIM], acc1[O_DIM];
#pragma unroll
    for (int o = 0; o < O_DIM; o++) { acc0[o] = 0.0f; acc1[o] = 0.0f; }

    float2 pf[5];
#pragma unroll
    for (int j = 0; j < 5; j++) pf[j] = p[(size_t)j * fstride];

#pragma unroll 1
    for (int fb = 0; fb < FCH; fb += 5) {
        float2 cur[5];
#pragma unroll
        for (int j = 0; j < 5; j++) cur[j] = pf[j];

#pragma unroll
        for (int j = 0; j < 5; j++) {
            int fn = fb + 5 + j;
            fn = (fn < FCH) ? fn : (FCH - 1);
            pf[j] = p[(size_t)fn * fstride];
        }

#pragma unroll
        for (int j = 0; j < 5; j++) {
            float s0 = fast_sigmoid(cur[j].x);
            float s1 = fast_sigmoid(cur[j].y);
            const float* row = Wt + (fb + j) * 12;
            float4 wa = *(const float4*)(row);
            float4 wb = *(const float4*)(row + 4);
            float2 wc = *(const float2*)(row + 8);
            float wv[O_DIM];
            wv[0] = wa.x; wv[1] = wa.y; wv[2] = wa.z; wv[3] = wa.w;
            wv[4] = wb.x; wv[5] = wb.y; wv[6] = wb.z; wv[7] = wb.w;
            wv[8] = wc.x; wv[9] = wc.y;
#pragma unroll
            for (int o = 0; o < O_DIM; o++) {
                acc0[o] = fmaf(s0, wv[o], acc0[o]);
                acc1[o] = fmaf(s1, wv[o], acc1[o]);
            }
        }
    }

    float* base = &g_part[z][b * O_DIM][0] + t0;
#pragma unroll
    for (int o = 0; o < O_DIM; o++) {
        float2 v; v.x = acc0[o]; v.y = acc1[o];
        *(float2*)(base + (size_t)o * T_DIM) = v;
    }
}

// ---------------------------------------------------------------------------
// Kernel 2 (fused merge + segment-parallel IIR/LIF). grid (20, 8), 128 thr.
// Phase 1: all threads load+reduce the 256t x 32chain window from 10 partials
//          (coalesced 512B warp reads) into smem xs4[t4][chain] (stride 33,
//          conflict-free). Seg-0 warmup half = zeros.
// Phase 2: warp 0 runs 128-step warmup (residual dm^128 ~1e-13 < fp32 ulp;
//          exact after any spike reset) + 128 output steps; spikes staged
//          into freed xs4 slots; transposed write = contiguous 512B rows.
// ---------------------------------------------------------------------------
__global__ __launch_bounds__(128) void k_lif(const float* __restrict__ a1v,
                                             const float* __restrict__ a2v,
                                             const float* __restrict__ bias,
                                             float* __restrict__ out) {
    __shared__ float4 xs4[64 * 33];    // [t4 0..63][chain 0..31], stride 33

    const int tid  = threadIdx.x;
    const int lane = tid & 31;
    const int wid  = tid >> 5;
    const int bo0  = blockIdx.x * 32;
    const int seg  = blockIdx.y;
    const int t0   = seg * 128 - 128;  // global t of window start (warmup half)

    // ---- phase 1: load + reduce + transpose-store ----
    if (seg > 0) {
#pragma unroll 4
        for (int k = 0; k < 16; k++) {
            int pos  = tid + 128 * k;      // 0..2047
            int quad = pos & 63;           // t4 within window
            int r    = pos >> 6;           // chain within tile
            const float* gp = &g_part[0][bo0 + r][0] + t0 + 4 * quad;
            float4 acc = make_float4(0.f, 0.f, 0.f, 0.f);
#pragma unroll
            for (int z = 0; z < FSPLIT; z++) {
                float4 v = *(const float4*)(gp + (size_t)z * BO * T_DIM);
                acc.x += v.x; acc.y += v.y; acc.z += v.z; acc.w += v.w;
            }
            xs4[quad * 33 + r] = acc;
        }
    } else {
#pragma unroll 4
        for (int k = 0; k < 16; k++) {
            int pos  = tid + 128 * k;
            int quad = pos & 63;
            int r    = pos >> 6;
            float4 acc = make_float4(0.f, 0.f, 0.f, 0.f);
            if (quad >= 32) {              // main half only; warmup half = zeros
                const float* gp = &g_part[0][bo0 + r][0] + t0 + 4 * quad;
#pragma unroll
                for (int z = 0; z < FSPLIT; z++) {
                    float4 v = *(const float4*)(gp + (size_t)z * BO * T_DIM);
                    acc.x += v.x; acc.y += v.y; acc.z += v.z; acc.w += v.w;
                }
            }
            xs4[quad * 33 + r] = acc;
        }
    }
    __syncthreads();

    if (wid != 0) return;              // warps 1-3 done (no further block syncs)

    // ---- phase 2: warp 0, 32 chains ----
    const int bo = bo0 + lane;
    const float A1 = a1v[0];
    const float A2 = a2v[0];
    const float dm = 0.5f * (A1 + sqrtf(fmaf(A1, A1, 4.0f * A2)));
    const float bb  = bias[bo % O_DIM];
    const float bwu = (seg == 0) ? 0.0f : bb;

    float y1 = 0.0f, y2 = 0.0f, v = 0.0f;
    bool sp = false;

    // warmup: t4 0..31, no output
#pragma unroll 8
    for (int t4 = 0; t4 < 32; t4++) {
        float4 x4 = xs4[t4 * 33 + lane];
#pragma unroll
        for (int k = 0; k < 4; k++) {
            float x = (k == 0) ? x4.x : (k == 1) ? x4.y : (k == 2) ? x4.z : x4.w;
            float y = fmaf(A1, y1, fmaf(A2, y2, x));
            y2 = y1; y1 = y;
            float psc = y + bwu;
            float vns = fmaf(dm, v, psc);
            v  = sp ? psc : vns;
            sp = (v > 1.0f);
        }
    }

    // main: t4 32..63, spikes staged back into the slot just consumed
#pragma unroll 8
    for (int t4 = 32; t4 < 64; t4++) {
        float4 x4 = xs4[t4 * 33 + lane];
        float4 os;
#pragma unroll
        for (int k = 0; k < 4; k++) {
            float x = (k == 0) ? x4.x : (k == 1) ? x4.y : (k == 2) ? x4.z : x4.w;
            float y = fmaf(A1, y1, fmaf(A2, y2, x));
            y2 = y1; y1 = y;
            float psc = y + bb;
            float vns = fmaf(dm, v, psc);
            v  = sp ? psc : vns;
            sp = (v > 1.0f);
            float s = sp ? 1.0f : 0.0f;
            if      (k == 0) os.x = s;
            else if (k == 1) os.y = s;
            else if (k == 2) os.z = s;
            else             os.w = s;
        }
        xs4[t4 * 33 + lane] = os;
    }
    __syncwarp();

    // transposed write: row r, lane covers t4 -> contiguous 512B per row
#pragma unroll 4
    for (int r = 0; r < 32; r++) {
        float4 w = xs4[(32 + lane) * 33 + r];
        *(float4*)(out + (size_t)(bo0 + r) * T_DIM + seg * 128 + lane * 4) = w;
    }
}

// ---------------------------------------------------------------------------
extern "C" void kernel_launch(void* const* d_in, const int* in_sizes, int n_in,
                              void* d_out, int out_size) {
    const float* in  = (const float*)d_in[0];   // [64, 500, 1024]
    const float* a1  = (const float*)d_in[1];   // [500]
    const float* a2  = (const float*)d_in[2];   // [500]
    const float* W   = (const float*)d_in[3];   // [10, 500]
    const float* bv  = (const float*)d_in[4];   // [10]
    float* out = (float*)d_out;                 // [64, 10, 1024]

    k_proj<<<dim3(T_DIM / 256, B_DIM, FSPLIT), 128>>>(in, W);
    k_lif<<<dim3(BO / 32, T_DIM / 128), 128>>>(a1, a2, bv, out);
}